// round 10
// baseline (speedup 1.0000x reference)
#include <cuda_runtime.h>
#include <math.h>

// Problem constants (fixed by the dataset)
#define NN 50000
#define EE 800000
#define HID 64
#define OUTC 8
#define NEG_SLOPE 0.2f

// ---------------- device scratch (no allocations allowed) ----------------
__device__ int g_is64;                        // 1 if edge_index is int64
__device__ __align__(16) int   g_deg[NN];
__device__ __align__(16) int   g_rowptr[NN + 1];
__device__ __align__(16) int   g_cursor[NN];
__device__ __align__(16) int   g_ssrc[EE];    // src ids sorted by dst
__device__ __align__(16) float g_sval[EE];    // edge_value sorted by dst
__device__ __align__(16) float g_h1[NN * HID];
__device__ __align__(16) float g_es1[NN];
__device__ __align__(16) float g_ed1[NN];
__device__ __align__(16) float g_hid[NN * HID];
__device__ __align__(16) float g_h2[NN * OUTC];
__device__ __align__(16) float g_es2[NN];
__device__ __align__(16) float g_ed2[NN];

__device__ __forceinline__ float leaky(float x) {
    return x > 0.f ? x : NEG_SLOPE * x;
}

__device__ __forceinline__ int clampN(int s) {
    return ((unsigned)s < NN) ? s : 0;
}

// Fetch an edge-index element honoring the detected dtype (32-bit loads only).
__device__ __forceinline__ int ei_at(const int* ei32, long long idx, int is64) {
    return is64 ? ei32[2 * idx] : ei32[idx];
}

// ---------------- dtype detector (4-byte loads only; alignment-safe) -------
// int64 data (values < 50000): every odd u32 word of the first 2048 elements
// is the zero high-half. int32 data: those words are random src ids.
__global__ void k_detect(const int* __restrict__ ei32) {
    int bad = 0;
    for (int i = threadIdx.x; i < 2048; i += blockDim.x) {
        if (ei32[2 * i + 1] != 0) bad = 1;
    }
    int any = __syncthreads_or(bad);
    if (threadIdx.x == 0) g_is64 = any ? 0 : 1;
}

// ---------------- CSR build ----------------
__global__ void k_zero_deg() {
    int i = blockIdx.x * blockDim.x + threadIdx.x;
    if (i < NN) g_deg[i] = 0;
}

__global__ void k_hist(const int* __restrict__ ei32) {
    int e = blockIdx.x * blockDim.x + threadIdx.x;
    if (e < EE) {
        int d = ei_at(ei32, (long long)EE + e, g_is64);
        if ((unsigned)d < NN) atomicAdd(&g_deg[d], 1);
    }
}

// single block, 1024 threads: exclusive scan of deg -> rowptr + cursor
__global__ void k_scan() {
    __shared__ int sums[1024];
    const int CH = (NN + 1023) / 1024;
    int t = threadIdx.x;
    int b = t * CH;
    int en = b + CH;
    if (en > NN) en = NN;
    if (b > NN) b = NN;
    int s = 0;
    for (int i = b; i < en; i++) s += g_deg[i];
    sums[t] = s;
    __syncthreads();
    for (int off = 1; off < 1024; off <<= 1) {
        int v = sums[t];
        int add = (t >= off) ? sums[t - off] : 0;
        __syncthreads();
        sums[t] = v + add;
        __syncthreads();
    }
    int run = (t == 0) ? 0 : sums[t - 1];
    for (int i = b; i < en; i++) {
        int dv = g_deg[i];
        g_rowptr[i] = run;
        g_cursor[i] = run;
        run += dv;
    }
    if (t == 1023) g_rowptr[NN] = sums[1023];
}

__global__ void k_scatter(const int* __restrict__ ei32,
                          const float* __restrict__ ev) {
    int e = blockIdx.x * blockDim.x + threadIdx.x;
    if (e < EE) {
        int is64 = g_is64;
        int s = ei_at(ei32, e, is64);
        int d = ei_at(ei32, (long long)EE + e, is64);
        if ((unsigned)s < NN && (unsigned)d < NN) {
            int pos = atomicAdd(&g_cursor[d], 1);
            if ((unsigned)pos < EE) {
                g_ssrc[pos] = s;
                g_sval[pos] = ev[e];
            }
        }
    }
}

// ---------------- layer 1: h1 = x @ W1 ; e_src/e_dst dots ----------------
// 256 threads = 4 nodes x 64 channels; N % 4 == 0.
__global__ void k_gemm1(const float* __restrict__ x, const float* __restrict__ W1,
                        const float* __restrict__ a1s, const float* __restrict__ a1d) {
    __shared__ float Ws[64 * 64];
    __shared__ float xs[4 * 64];
    __shared__ float ps[8], pd[8];
    int t = threadIdx.x;
    #pragma unroll
    for (int i = t; i < 4096; i += 256) Ws[i] = W1[i];
    int base = blockIdx.x * 4;
    xs[t] = x[base * 64 + t];
    __syncthreads();
    int nl = t >> 6, c = t & 63;
    float sum = 0.f;
    #pragma unroll
    for (int k = 0; k < 64; k++) sum = fmaf(xs[nl * 64 + k], Ws[k * 64 + c], sum);
    int n = base + nl;
    g_h1[n * 64 + c] = sum;
    float vs = sum * a1s[c];
    float vd = sum * a1d[c];
    #pragma unroll
    for (int off = 16; off; off >>= 1) {
        vs += __shfl_xor_sync(0xffffffffu, vs, off);
        vd += __shfl_xor_sync(0xffffffffu, vd, off);
    }
    if ((t & 31) == 0) { ps[t >> 5] = vs; pd[t >> 5] = vd; }
    __syncthreads();
    if (c == 0) {
        g_es1[n] = ps[2 * nl] + ps[2 * nl + 1];
        g_ed1[n] = pd[2 * nl] + pd[2 * nl + 1];
    }
}

// ---------------- layer 1 aggregate: warp per dst node ----------------
__global__ void k_agg1(const float* __restrict__ b1) {
    int w = (blockIdx.x * blockDim.x + threadIdx.x) >> 5;
    if (w >= NN) return;
    int lane = threadIdx.x & 31;
    int s0 = g_rowptr[w], s1 = g_rowptr[w + 1];
    s0 = max(0, min(s0, EE));
    s1 = max(s0, min(s1, EE));
    int deg = s1 - s0;
    float ed = g_ed1[w];
    int c2 = lane * 2;
    float a0 = 0.f, a1 = 0.f;

    if (deg <= 32) {
        // fast path: one edge per lane; weights & srcs broadcast by shuffle.
        // All loops below have warp-uniform trip counts (deg is uniform).
        int   sle = 0;
        float evl = 0.f, l = -INFINITY;
        if (lane < deg) {
            sle = clampN(g_ssrc[s0 + lane]);
            evl = g_sval[s0 + lane];
            l   = leaky(g_es1[sle] + ed);
        }
        float m = l;
        #pragma unroll
        for (int off = 16; off; off >>= 1) m = fmaxf(m, __shfl_xor_sync(0xffffffffu, m, off));
        float ex = (lane < deg) ? __expf(l - m) : 0.f;
        float den = ex;
        #pragma unroll
        for (int off = 16; off; off >>= 1) den += __shfl_xor_sync(0xffffffffu, den, off);
        float wgt = ex * evl / (den + 1e-16f);
        int j = 0;
        for (; j + 1 < deg; j += 2) {
            float w0 = __shfl_sync(0xffffffffu, wgt, j);
            int   sa = __shfl_sync(0xffffffffu, sle, j);
            float w1 = __shfl_sync(0xffffffffu, wgt, j + 1);
            int   sb = __shfl_sync(0xffffffffu, sle, j + 1);
            float2 ha = *(const float2*)(g_h1 + sa * 64 + c2);
            float2 hb = *(const float2*)(g_h1 + sb * 64 + c2);
            a0 = fmaf(w0, ha.x, a0); a1 = fmaf(w0, ha.y, a1);
            a0 = fmaf(w1, hb.x, a0); a1 = fmaf(w1, hb.y, a1);
        }
        if (j < deg) {
            float w0 = __shfl_sync(0xffffffffu, wgt, j);
            int   sa = __shfl_sync(0xffffffffu, sle, j);
            float2 ha = *(const float2*)(g_h1 + sa * 64 + c2);
            a0 = fmaf(w0, ha.x, a0); a1 = fmaf(w0, ha.y, a1);
        }
    } else {
        // general path: 3-pass (no shuffles inside divergent loops)
        float m = -INFINITY;
        for (int i = s0 + lane; i < s1; i += 32)
            m = fmaxf(m, leaky(g_es1[clampN(g_ssrc[i])] + ed));
        #pragma unroll
        for (int off = 16; off; off >>= 1) m = fmaxf(m, __shfl_xor_sync(0xffffffffu, m, off));
        float den = 0.f;
        for (int i = s0 + lane; i < s1; i += 32)
            den += __expf(leaky(g_es1[clampN(g_ssrc[i])] + ed) - m);
        #pragma unroll
        for (int off = 16; off; off >>= 1) den += __shfl_xor_sync(0xffffffffu, den, off);
        float scale = 1.f / (den + 1e-16f);
        int i = s0;
        for (; i + 1 < s1; i += 2) {
            int sa = clampN(g_ssrc[i]);
            int sb = clampN(g_ssrc[i + 1]);
            float wa = __expf(leaky(g_es1[sa] + ed) - m) * scale * g_sval[i];
            float wb = __expf(leaky(g_es1[sb] + ed) - m) * scale * g_sval[i + 1];
            float2 ha = *(const float2*)(g_h1 + sa * 64 + c2);
            float2 hb = *(const float2*)(g_h1 + sb * 64 + c2);
            a0 = fmaf(wa, ha.x, a0); a1 = fmaf(wa, ha.y, a1);
            a0 = fmaf(wb, hb.x, a0); a1 = fmaf(wb, hb.y, a1);
        }
        if (i < s1) {
            int sa = clampN(g_ssrc[i]);
            float wa = __expf(leaky(g_es1[sa] + ed) - m) * scale * g_sval[i];
            float2 ha = *(const float2*)(g_h1 + sa * 64 + c2);
            a0 = fmaf(wa, ha.x, a0); a1 = fmaf(wa, ha.y, a1);
        }
    }
    float o0 = a0 + b1[c2];
    float o1 = a1 + b1[c2 + 1];
    g_hid[w * 64 + c2]     = o0 > 0.f ? o0 : 0.f;   // fused ReLU
    g_hid[w * 64 + c2 + 1] = o1 > 0.f ? o1 : 0.f;
}

// ---------------- layer 2: h2 = hid @ W2 ; attention dots ----------------
// 256 threads = 32 nodes x 8 channels
__global__ void k_gemm2(const float* __restrict__ W2,
                        const float* __restrict__ a2s, const float* __restrict__ a2d) {
    __shared__ float Ws[64 * 8];
    __shared__ float hs[32 * 65];
    int t = threadIdx.x;
    for (int i = t; i < 512; i += 256) Ws[i] = W2[i];
    int base = blockIdx.x * 32;
    for (int i = t; i < 2048; i += 256) {
        int nl = i >> 6, k = i & 63;
        int n = base + nl;
        hs[nl * 65 + k] = (n < NN) ? g_hid[n * 64 + k] : 0.f;
    }
    __syncthreads();
    int nl = t >> 3, c = t & 7;
    int n = base + nl;
    float sum = 0.f;
    #pragma unroll
    for (int k = 0; k < 64; k++) sum = fmaf(hs[nl * 65 + k], Ws[k * 8 + c], sum);
    float vs = sum * a2s[c];
    float vd = sum * a2d[c];
    #pragma unroll
    for (int off = 4; off; off >>= 1) {
        vs += __shfl_down_sync(0xffffffffu, vs, off);
        vd += __shfl_down_sync(0xffffffffu, vd, off);
    }
    if (n < NN) {
        g_h2[n * 8 + c] = sum;
        if (c == 0) { g_es2[n] = vs; g_ed2[n] = vd; }
    }
}

// ---------------- layer 2 aggregate + bias + log_softmax ----------------
__global__ void k_agg2(const float* __restrict__ b2, float* __restrict__ out) {
    int w = (blockIdx.x * blockDim.x + threadIdx.x) >> 5;
    if (w >= NN) return;
    int lane = threadIdx.x & 31;
    int s0 = g_rowptr[w], s1 = g_rowptr[w + 1];
    s0 = max(0, min(s0, EE));
    s1 = max(s0, min(s1, EE));
    int deg = s1 - s0;
    float ed = g_ed2[w];
    int g = lane >> 3, c = lane & 7;
    float acc = 0.f;

    if (deg <= 32) {
        int   sle = 0;
        float evl = 0.f, l = -INFINITY;
        if (lane < deg) {
            sle = clampN(g_ssrc[s0 + lane]);
            evl = g_sval[s0 + lane];
            l   = leaky(g_es2[sle] + ed);
        }
        float m = l;
        #pragma unroll
        for (int off = 16; off; off >>= 1) m = fmaxf(m, __shfl_xor_sync(0xffffffffu, m, off));
        float ex = (lane < deg) ? __expf(l - m) : 0.f;
        float den = ex;
        #pragma unroll
        for (int off = 16; off; off >>= 1) den += __shfl_xor_sync(0xffffffffu, den, off);
        float wgt = ex * evl / (den + 1e-16f);
        // UNIFORM trip count: all 32 lanes execute every shuffle; only the
        // accumulate is predicated. (Previous divergent-loop version was UB.)
        int nj = (deg + 3) >> 2;
        for (int jj = 0; jj < nj; jj++) {
            int j = jj * 4 + g;               // this lane's edge in group jj
            float wj = __shfl_sync(0xffffffffu, wgt, j & 31);
            int   sj = __shfl_sync(0xffffffffu, sle, j & 31);
            if (j < deg) acc = fmaf(wj, g_h2[sj * 8 + c], acc);
        }
    } else {
        float m = -INFINITY;
        for (int i = s0 + lane; i < s1; i += 32)
            m = fmaxf(m, leaky(g_es2[clampN(g_ssrc[i])] + ed));
        #pragma unroll
        for (int off = 16; off; off >>= 1) m = fmaxf(m, __shfl_xor_sync(0xffffffffu, m, off));
        float den = 0.f;
        for (int i = s0 + lane; i < s1; i += 32)
            den += __expf(leaky(g_es2[clampN(g_ssrc[i])] + ed) - m);
        #pragma unroll
        for (int off = 16; off; off >>= 1) den += __shfl_xor_sync(0xffffffffu, den, off);
        float scale = 1.f / (den + 1e-16f);
        for (int i = s0 + g; i < s1; i += 4) {   // no shuffles inside
            int s = clampN(g_ssrc[i]);
            float wgt = __expf(leaky(g_es2[s] + ed) - m) * scale * g_sval[i];
            acc = fmaf(wgt, g_h2[s * 8 + c], acc);
        }
    }
    acc += __shfl_down_sync(0xffffffffu, acc, 16);
    acc += __shfl_down_sync(0xffffffffu, acc, 8);
    // lanes 0..7 hold the 8 output channels (all lanes run the shuffles)
    float v = acc + b2[c];
    float mx = v;
    #pragma unroll
    for (int off = 1; off < 8; off <<= 1) mx = fmaxf(mx, __shfl_xor_sync(0xffffffffu, mx, off));
    float ex2 = __expf(v - mx);
    float sm = ex2;
    #pragma unroll
    for (int off = 1; off < 8; off <<= 1) sm += __shfl_xor_sync(0xffffffffu, sm, off);
    if (lane < 8) out[w * 8 + c] = v - mx - logf(sm);
}

// ---------------- launch ----------------
extern "C" void kernel_launch(void* const* d_in, const int* in_sizes, int n_in,
                              void* d_out, int out_size) {
    // Identify tensors by size; tolerate in_sizes being ELEMENTS or BYTES.
    // Sentinel: W1 = 4096 elements vs 16384 bytes (neither collides).
    int bytes_mode = 0;
    {
        int saw4096 = 0, saw16384 = 0;
        for (int i = 0; i < n_in; i++) {
            if (in_sizes[i] == 4096)  saw4096 = 1;
            if (in_sizes[i] == 16384) saw16384 = 1;
        }
        if (!saw4096 && saw16384) bytes_mode = 1;
    }
    const float* x = 0; const int* ei = 0; const float* ev = 0;
    const float* W1 = 0; const float* W2 = 0;
    const float *a1s = 0, *a1d = 0, *b1 = 0, *a2s = 0, *a2d = 0, *b2 = 0;
    int n64 = 0, n8 = 0;
    for (int i = 0; i < n_in; i++) {
        int s = in_sizes[i];
        const void* p = d_in[i];
        if (!bytes_mode) {
            if      (s == NN * HID)   x  = (const float*)p;
            else if (s == 2 * EE)     ei = (const int*)p;
            else if (s == EE)         ev = (const float*)p;
            else if (s == HID * HID)  W1 = (const float*)p;
            else if (s == HID * OUTC) W2 = (const float*)p;
            else if (s == HID) { if (n64 == 0) a1s = (const float*)p; else if (n64 == 1) a1d = (const float*)p; else b1 = (const float*)p; n64++; }
            else if (s == OUTC) { if (n8 == 0) a2s = (const float*)p; else if (n8 == 1) a2d = (const float*)p; else b2 = (const float*)p; n8++; }
        } else {
            if (s == NN * HID * 4) { if (!x) x = (const float*)p; else if (!ei) ei = (const int*)p; }  // x=12.8MB; int64 ei also 12.8MB (x first in order)
            else if (s == 2 * EE * 4) ei = (const int*)p;      // int32 ei, 6.4MB
            else if (s == EE * 4)     ev = (const float*)p;
            else if (s == HID * HID * 4)  W1 = (const float*)p;
            else if (s == HID * OUTC * 4) W2 = (const float*)p;
            else if (s == HID * 4) { if (n64 == 0) a1s = (const float*)p; else if (n64 == 1) a1d = (const float*)p; else b1 = (const float*)p; n64++; }
            else if (s == OUTC * 4) { if (n8 == 0) a2s = (const float*)p; else if (n8 == 1) a2d = (const float*)p; else b2 = (const float*)p; n8++; }
        }
    }
    // Positional fallback, never past n_in.
    if (!x   && n_in > 0)  x   = (const float*)d_in[0];
    if (!ei  && n_in > 1)  ei  = (const int*)d_in[1];
    if (!ev  && n_in > 2)  ev  = (const float*)d_in[2];
    if (!W1  && n_in > 3)  W1  = (const float*)d_in[3];
    if (!a1s && n_in > 4)  a1s = (const float*)d_in[4];
    if (!a1d && n_in > 5)  a1d = (const float*)d_in[5];
    if (!b1  && n_in > 6)  b1  = (const float*)d_in[6];
    if (!W2  && n_in > 7)  W2  = (const float*)d_in[7];
    if (!a2s && n_in > 8)  a2s = (const float*)d_in[8];
    if (!a2d && n_in > 9)  a2d = (const float*)d_in[9];
    if (!b2  && n_in > 10) b2  = (const float*)d_in[10];
    if (!x || !ei || !ev || !W1 || !a1s || !a1d || !b1 || !W2 || !a2s || !a2d || !b2)
        return;  // cannot run safely; harness will report mismatch, not a crash
    float* out = (float*)d_out;

    k_detect<<<1, 256>>>(ei);
    k_zero_deg<<<(NN + 255) / 256, 256>>>();
    k_hist<<<(EE + 255) / 256, 256>>>(ei);
    k_scan<<<1, 1024>>>();
    k_scatter<<<(EE + 255) / 256, 256>>>(ei, ev);

    k_gemm1<<<NN / 4, 256>>>(x, W1, a1s, a1d);
    k_agg1<<<(NN * 32 + 255) / 256, 256>>>(b1);
    k_gemm2<<<(NN + 31) / 32, 256>>>(W2, a2s, a2d);
    k_agg2<<<(NN * 32 + 255) / 256, 256>>>(b2, out);
}

// round 11
// speedup vs baseline: 1.5060x; 1.5060x over previous
#include <cuda_runtime.h>
#include <math.h>

// Problem constants (fixed by the dataset)
#define NN 50000
#define EE 800000
#define HID 64
#define OUTC 8
#define NEG_SLOPE 0.2f

// scan geometry
#define SCAN_T 256
#define SCAN_NB ((NN + SCAN_T - 1) / SCAN_T)   // 196

// ---------------- device scratch (no allocations allowed) ----------------
__device__ int g_is64;                        // 1 if edge_index is int64
__device__ __align__(16) int   g_deg[NN];
__device__ __align__(16) int   g_psum[NN];    // per-element block-local exclusive scan
__device__ __align__(16) int   g_bsum[SCAN_NB + 1];
__device__ __align__(16) int   g_rowptr[NN + 1];
__device__ __align__(16) int   g_cursor[NN];
__device__ __align__(16) int   g_ssrc[EE];    // src ids sorted by dst
__device__ __align__(16) float g_sval[EE];    // edge_value sorted by dst
__device__ __align__(16) float g_h1[NN * HID];
__device__ __align__(16) float g_es1[NN];
__device__ __align__(16) float g_ed1[NN];
__device__ __align__(16) float g_hid[NN * HID];
__device__ __align__(16) float g_h2[NN * OUTC];
__device__ __align__(16) float g_es2[NN];
__device__ __align__(16) float g_ed2[NN];

__device__ __forceinline__ float leaky(float x) {
    return x > 0.f ? x : NEG_SLOPE * x;
}

__device__ __forceinline__ int clampN(int s) {
    return ((unsigned)s < NN) ? s : 0;
}

// Fetch an edge-index element honoring the detected dtype (32-bit loads only).
__device__ __forceinline__ int ei_at(const int* ei32, long long idx, int is64) {
    return is64 ? ei32[2 * idx] : ei32[idx];
}

// ---------------- dtype detector (4-byte loads only; alignment-safe) -------
__global__ void k_detect(const int* __restrict__ ei32) {
    int bad = 0;
    for (int i = threadIdx.x; i < 2048; i += blockDim.x) {
        if (ei32[2 * i + 1] != 0) bad = 1;
    }
    int any = __syncthreads_or(bad);
    if (threadIdx.x == 0) g_is64 = any ? 0 : 1;
}

// ---------------- CSR build ----------------
__global__ void k_zero_deg() {
    int i = blockIdx.x * blockDim.x + threadIdx.x;
    if (i < NN) g_deg[i] = 0;
}

__global__ void k_hist(const int* __restrict__ ei32) {
    int e = blockIdx.x * blockDim.x + threadIdx.x;
    if (e < EE) {
        int d = ei_at(ei32, (long long)EE + e, g_is64);
        if ((unsigned)d < NN) atomicAdd(&g_deg[d], 1);
    }
}

// ---- 3-phase grid-wide exclusive scan (replaces the 77us 1-block scan) ----
// Phase 1: per-block exclusive scan of 256 deg values + block total.
__global__ void k_scan_blk() {
    __shared__ int sh[SCAN_T];
    int t = threadIdx.x;
    int i = blockIdx.x * SCAN_T + t;
    int v = (i < NN) ? g_deg[i] : 0;
    sh[t] = v;
    __syncthreads();
    // Hillis-Steele inclusive scan over 256 values (8 steps)
    #pragma unroll
    for (int off = 1; off < SCAN_T; off <<= 1) {
        int add = (t >= off) ? sh[t - off] : 0;
        __syncthreads();
        sh[t] += add;
        __syncthreads();
    }
    if (i < NN) g_psum[i] = sh[t] - v;           // exclusive
    if (t == SCAN_T - 1) g_bsum[blockIdx.x] = sh[t];  // block total
}

// Phase 2: single small block scans the 196 block totals (exclusive, in place)
__global__ void k_scan_top() {
    __shared__ int sh[SCAN_NB];
    int t = threadIdx.x;
    int v = (t < SCAN_NB) ? g_bsum[t] : 0;
    if (t < SCAN_NB) sh[t] = v;
    __syncthreads();
    for (int off = 1; off < SCAN_NB; off <<= 1) {
        int add = (t >= off && t < SCAN_NB) ? sh[t - off] : 0;
        __syncthreads();
        if (t < SCAN_NB) sh[t] += add;
        __syncthreads();
    }
    if (t < SCAN_NB) g_bsum[t] = sh[t] - v;      // exclusive block offsets
    if (t == SCAN_NB - 1) g_rowptr[NN] = sh[t];  // total edge count
}

// Phase 3: add block offsets -> rowptr + cursor
__global__ void k_scan_add() {
    int i = blockIdx.x * blockDim.x + threadIdx.x;
    if (i < NN) {
        int r = g_bsum[blockIdx.x] + g_psum[i];  // blockDim == SCAN_T
        g_rowptr[i] = r;
        g_cursor[i] = r;
    }
}

__global__ void k_scatter(const int* __restrict__ ei32,
                          const float* __restrict__ ev) {
    int e = blockIdx.x * blockDim.x + threadIdx.x;
    if (e < EE) {
        int is64 = g_is64;
        int s = ei_at(ei32, e, is64);
        int d = ei_at(ei32, (long long)EE + e, is64);
        if ((unsigned)s < NN && (unsigned)d < NN) {
            int pos = atomicAdd(&g_cursor[d], 1);
            if ((unsigned)pos < EE) {
                g_ssrc[pos] = s;
                g_sval[pos] = ev[e];
            }
        }
    }
}

// ---------------- layer 1: h1 = x @ W1 ; e_src/e_dst dots ----------------
// 256 threads = 4 nodes x 64 channels; N % 4 == 0.
__global__ void k_gemm1(const float* __restrict__ x, const float* __restrict__ W1,
                        const float* __restrict__ a1s, const float* __restrict__ a1d) {
    __shared__ float Ws[64 * 64];
    __shared__ float xs[4 * 64];
    __shared__ float ps[8], pd[8];
    int t = threadIdx.x;
    #pragma unroll
    for (int i = t; i < 4096; i += 256) Ws[i] = W1[i];
    int base = blockIdx.x * 4;
    xs[t] = x[base * 64 + t];
    __syncthreads();
    int nl = t >> 6, c = t & 63;
    float sum = 0.f;
    #pragma unroll
    for (int k = 0; k < 64; k++) sum = fmaf(xs[nl * 64 + k], Ws[k * 64 + c], sum);
    int n = base + nl;
    g_h1[n * 64 + c] = sum;
    float vs = sum * a1s[c];
    float vd = sum * a1d[c];
    #pragma unroll
    for (int off = 16; off; off >>= 1) {
        vs += __shfl_xor_sync(0xffffffffu, vs, off);
        vd += __shfl_xor_sync(0xffffffffu, vd, off);
    }
    if ((t & 31) == 0) { ps[t >> 5] = vs; pd[t >> 5] = vd; }
    __syncthreads();
    if (c == 0) {
        g_es1[n] = ps[2 * nl] + ps[2 * nl + 1];
        g_ed1[n] = pd[2 * nl] + pd[2 * nl + 1];
    }
}

// ---------------- layer 1 aggregate: warp per dst node ----------------
__global__ void k_agg1(const float* __restrict__ b1) {
    int w = (blockIdx.x * blockDim.x + threadIdx.x) >> 5;
    if (w >= NN) return;
    int lane = threadIdx.x & 31;
    int s0 = g_rowptr[w], s1 = g_rowptr[w + 1];
    s0 = max(0, min(s0, EE));
    s1 = max(s0, min(s1, EE));
    int deg = s1 - s0;
    float ed = g_ed1[w];
    int c2 = lane * 2;
    float a0 = 0.f, a1 = 0.f;

    if (deg <= 32) {
        // fast path: one edge per lane; weights & srcs broadcast by shuffle.
        int   sle = 0;
        float evl = 0.f, l = -INFINITY;
        if (lane < deg) {
            sle = clampN(g_ssrc[s0 + lane]);
            evl = g_sval[s0 + lane];
            l   = leaky(g_es1[sle] + ed);
        }
        float m = l;
        #pragma unroll
        for (int off = 16; off; off >>= 1) m = fmaxf(m, __shfl_xor_sync(0xffffffffu, m, off));
        float ex = (lane < deg) ? __expf(l - m) : 0.f;
        float den = ex;
        #pragma unroll
        for (int off = 16; off; off >>= 1) den += __shfl_xor_sync(0xffffffffu, den, off);
        float wgt = ex * evl / (den + 1e-16f);
        int j = 0;
        for (; j + 1 < deg; j += 2) {
            float w0 = __shfl_sync(0xffffffffu, wgt, j);
            int   sa = __shfl_sync(0xffffffffu, sle, j);
            float w1 = __shfl_sync(0xffffffffu, wgt, j + 1);
            int   sb = __shfl_sync(0xffffffffu, sle, j + 1);
            float2 ha = *(const float2*)(g_h1 + sa * 64 + c2);
            float2 hb = *(const float2*)(g_h1 + sb * 64 + c2);
            a0 = fmaf(w0, ha.x, a0); a1 = fmaf(w0, ha.y, a1);
            a0 = fmaf(w1, hb.x, a0); a1 = fmaf(w1, hb.y, a1);
        }
        if (j < deg) {
            float w0 = __shfl_sync(0xffffffffu, wgt, j);
            int   sa = __shfl_sync(0xffffffffu, sle, j);
            float2 ha = *(const float2*)(g_h1 + sa * 64 + c2);
            a0 = fmaf(w0, ha.x, a0); a1 = fmaf(w0, ha.y, a1);
        }
    } else {
        // general path: 3-pass (no shuffles inside divergent loops)
        float m = -INFINITY;
        for (int i = s0 + lane; i < s1; i += 32)
            m = fmaxf(m, leaky(g_es1[clampN(g_ssrc[i])] + ed));
        #pragma unroll
        for (int off = 16; off; off >>= 1) m = fmaxf(m, __shfl_xor_sync(0xffffffffu, m, off));
        float den = 0.f;
        for (int i = s0 + lane; i < s1; i += 32)
            den += __expf(leaky(g_es1[clampN(g_ssrc[i])] + ed) - m);
        #pragma unroll
        for (int off = 16; off; off >>= 1) den += __shfl_xor_sync(0xffffffffu, den, off);
        float scale = 1.f / (den + 1e-16f);
        int i = s0;
        for (; i + 1 < s1; i += 2) {
            int sa = clampN(g_ssrc[i]);
            int sb = clampN(g_ssrc[i + 1]);
            float wa = __expf(leaky(g_es1[sa] + ed) - m) * scale * g_sval[i];
            float wb = __expf(leaky(g_es1[sb] + ed) - m) * scale * g_sval[i + 1];
            float2 ha = *(const float2*)(g_h1 + sa * 64 + c2);
            float2 hb = *(const float2*)(g_h1 + sb * 64 + c2);
            a0 = fmaf(wa, ha.x, a0); a1 = fmaf(wa, ha.y, a1);
            a0 = fmaf(wb, hb.x, a0); a1 = fmaf(wb, hb.y, a1);
        }
        if (i < s1) {
            int sa = clampN(g_ssrc[i]);
            float wa = __expf(leaky(g_es1[sa] + ed) - m) * scale * g_sval[i];
            float2 ha = *(const float2*)(g_h1 + sa * 64 + c2);
            a0 = fmaf(wa, ha.x, a0); a1 = fmaf(wa, ha.y, a1);
        }
    }
    float o0 = a0 + b1[c2];
    float o1 = a1 + b1[c2 + 1];
    g_hid[w * 64 + c2]     = o0 > 0.f ? o0 : 0.f;   // fused ReLU
    g_hid[w * 64 + c2 + 1] = o1 > 0.f ? o1 : 0.f;
}

// ---------------- layer 2: h2 = hid @ W2 ; attention dots ----------------
// 256 threads = 32 nodes x 8 channels
__global__ void k_gemm2(const float* __restrict__ W2,
                        const float* __restrict__ a2s, const float* __restrict__ a2d) {
    __shared__ float Ws[64 * 8];
    __shared__ float hs[32 * 65];
    int t = threadIdx.x;
    for (int i = t; i < 512; i += 256) Ws[i] = W2[i];
    int base = blockIdx.x * 32;
    for (int i = t; i < 2048; i += 256) {
        int nl = i >> 6, k = i & 63;
        int n = base + nl;
        hs[nl * 65 + k] = (n < NN) ? g_hid[n * 64 + k] : 0.f;
    }
    __syncthreads();
    int nl = t >> 3, c = t & 7;
    int n = base + nl;
    float sum = 0.f;
    #pragma unroll
    for (int k = 0; k < 64; k++) sum = fmaf(hs[nl * 65 + k], Ws[k * 8 + c], sum);
    float vs = sum * a2s[c];
    float vd = sum * a2d[c];
    #pragma unroll
    for (int off = 4; off; off >>= 1) {
        vs += __shfl_down_sync(0xffffffffu, vs, off);
        vd += __shfl_down_sync(0xffffffffu, vd, off);
    }
    if (n < NN) {
        g_h2[n * 8 + c] = sum;
        if (c == 0) { g_es2[n] = vs; g_ed2[n] = vd; }
    }
}

// ---------------- layer 2 aggregate + bias + log_softmax ----------------
__global__ void k_agg2(const float* __restrict__ b2, float* __restrict__ out) {
    int w = (blockIdx.x * blockDim.x + threadIdx.x) >> 5;
    if (w >= NN) return;
    int lane = threadIdx.x & 31;
    int s0 = g_rowptr[w], s1 = g_rowptr[w + 1];
    s0 = max(0, min(s0, EE));
    s1 = max(s0, min(s1, EE));
    int deg = s1 - s0;
    float ed = g_ed2[w];
    int g = lane >> 3, c = lane & 7;
    float acc = 0.f;

    if (deg <= 32) {
        int   sle = 0;
        float evl = 0.f, l = -INFINITY;
        if (lane < deg) {
            sle = clampN(g_ssrc[s0 + lane]);
            evl = g_sval[s0 + lane];
            l   = leaky(g_es2[sle] + ed);
        }
        float m = l;
        #pragma unroll
        for (int off = 16; off; off >>= 1) m = fmaxf(m, __shfl_xor_sync(0xffffffffu, m, off));
        float ex = (lane < deg) ? __expf(l - m) : 0.f;
        float den = ex;
        #pragma unroll
        for (int off = 16; off; off >>= 1) den += __shfl_xor_sync(0xffffffffu, den, off);
        float wgt = ex * evl / (den + 1e-16f);
        // UNIFORM trip count: all lanes run every shuffle; FMA predicated.
        int nj = (deg + 3) >> 2;
        for (int jj = 0; jj < nj; jj++) {
            int j = jj * 4 + g;
            float wj = __shfl_sync(0xffffffffu, wgt, j & 31);
            int   sj = __shfl_sync(0xffffffffu, sle, j & 31);
            if (j < deg) acc = fmaf(wj, g_h2[sj * 8 + c], acc);
        }
    } else {
        float m = -INFINITY;
        for (int i = s0 + lane; i < s1; i += 32)
            m = fmaxf(m, leaky(g_es2[clampN(g_ssrc[i])] + ed));
        #pragma unroll
        for (int off = 16; off; off >>= 1) m = fmaxf(m, __shfl_xor_sync(0xffffffffu, m, off));
        float den = 0.f;
        for (int i = s0 + lane; i < s1; i += 32)
            den += __expf(leaky(g_es2[clampN(g_ssrc[i])] + ed) - m);
        #pragma unroll
        for (int off = 16; off; off >>= 1) den += __shfl_xor_sync(0xffffffffu, den, off);
        float scale = 1.f / (den + 1e-16f);
        for (int i = s0 + g; i < s1; i += 4) {
            int s = clampN(g_ssrc[i]);
            float wgt = __expf(leaky(g_es2[s] + ed) - m) * scale * g_sval[i];
            acc = fmaf(wgt, g_h2[s * 8 + c], acc);
        }
    }
    acc += __shfl_down_sync(0xffffffffu, acc, 16);
    acc += __shfl_down_sync(0xffffffffu, acc, 8);
    float v = acc + b2[c];
    float mx = v;
    #pragma unroll
    for (int off = 1; off < 8; off <<= 1) mx = fmaxf(mx, __shfl_xor_sync(0xffffffffu, mx, off));
    float ex2 = __expf(v - mx);
    float sm = ex2;
    #pragma unroll
    for (int off = 1; off < 8; off <<= 1) sm += __shfl_xor_sync(0xffffffffu, sm, off);
    if (lane < 8) out[w * 8 + c] = v - mx - logf(sm);
}

// ---------------- launch ----------------
extern "C" void kernel_launch(void* const* d_in, const int* in_sizes, int n_in,
                              void* d_out, int out_size) {
    // Identify tensors by size; tolerate in_sizes being ELEMENTS or BYTES.
    int bytes_mode = 0;
    {
        int saw4096 = 0, saw16384 = 0;
        for (int i = 0; i < n_in; i++) {
            if (in_sizes[i] == 4096)  saw4096 = 1;
            if (in_sizes[i] == 16384) saw16384 = 1;
        }
        if (!saw4096 && saw16384) bytes_mode = 1;
    }
    const float* x = 0; const int* ei = 0; const float* ev = 0;
    const float* W1 = 0; const float* W2 = 0;
    const float *a1s = 0, *a1d = 0, *b1 = 0, *a2s = 0, *a2d = 0, *b2 = 0;
    int n64 = 0, n8 = 0;
    for (int i = 0; i < n_in; i++) {
        int s = in_sizes[i];
        const void* p = d_in[i];
        if (!bytes_mode) {
            if      (s == NN * HID)   x  = (const float*)p;
            else if (s == 2 * EE)     ei = (const int*)p;
            else if (s == EE)         ev = (const float*)p;
            else if (s == HID * HID)  W1 = (const float*)p;
            else if (s == HID * OUTC) W2 = (const float*)p;
            else if (s == HID) { if (n64 == 0) a1s = (const float*)p; else if (n64 == 1) a1d = (const float*)p; else b1 = (const float*)p; n64++; }
            else if (s == OUTC) { if (n8 == 0) a2s = (const float*)p; else if (n8 == 1) a2d = (const float*)p; else b2 = (const float*)p; n8++; }
        } else {
            if (s == NN * HID * 4) { if (!x) x = (const float*)p; else if (!ei) ei = (const int*)p; }
            else if (s == 2 * EE * 4) ei = (const int*)p;
            else if (s == EE * 4)     ev = (const float*)p;
            else if (s == HID * HID * 4)  W1 = (const float*)p;
            else if (s == HID * OUTC * 4) W2 = (const float*)p;
            else if (s == HID * 4) { if (n64 == 0) a1s = (const float*)p; else if (n64 == 1) a1d = (const float*)p; else b1 = (const float*)p; n64++; }
            else if (s == OUTC * 4) { if (n8 == 0) a2s = (const float*)p; else if (n8 == 1) a2d = (const float*)p; else b2 = (const float*)p; n8++; }
        }
    }
    if (!x   && n_in > 0)  x   = (const float*)d_in[0];
    if (!ei  && n_in > 1)  ei  = (const int*)d_in[1];
    if (!ev  && n_in > 2)  ev  = (const float*)d_in[2];
    if (!W1  && n_in > 3)  W1  = (const float*)d_in[3];
    if (!a1s && n_in > 4)  a1s = (const float*)d_in[4];
    if (!a1d && n_in > 5)  a1d = (const float*)d_in[5];
    if (!b1  && n_in > 6)  b1  = (const float*)d_in[6];
    if (!W2  && n_in > 7)  W2  = (const float*)d_in[7];
    if (!a2s && n_in > 8)  a2s = (const float*)d_in[8];
    if (!a2d && n_in > 9)  a2d = (const float*)d_in[9];
    if (!b2  && n_in > 10) b2  = (const float*)d_in[10];
    if (!x || !ei || !ev || !W1 || !a1s || !a1d || !b1 || !W2 || !a2s || !a2d || !b2)
        return;
    float* out = (float*)d_out;

    k_detect<<<1, 256>>>(ei);
    k_zero_deg<<<(NN + 255) / 256, 256>>>();
    k_hist<<<(EE + 255) / 256, 256>>>(ei);
    k_scan_blk<<<SCAN_NB, SCAN_T>>>();
    k_scan_top<<<1, 256>>>();
    k_scan_add<<<SCAN_NB, SCAN_T>>>();
    k_scatter<<<(EE + 255) / 256, 256>>>(ei, ev);

    k_gemm1<<<NN / 4, 256>>>(x, W1, a1s, a1d);
    k_agg1<<<(NN * 32 + 255) / 256, 256>>>(b1);
    k_gemm2<<<(NN + 31) / 32, 256>>>(W2, a2s, a2d);
    k_agg2<<<(NN * 32 + 255) / 256, 256>>>(b2, out);
}